// round 5
// baseline (speedup 1.0000x reference)
#include <cuda_runtime.h>

// EMA along last axis: acc_t = w*x_t + (1-w)*acc_{t-1}
// [B,C,F,T] fp32, T=6000 contiguous; 4112 independent sequences.
//
// TWO warps per sequence (8224 warps total -> ~56 warps/SM):
//   warp h=0: elements [0, 3072)    -- 24 segments, exact (uses init)
//   warp h=1: elements [3072, 6000) -- 22 full segs + 112-elem tail,
//             preceded by a dynamic zero-init warmup (a^(128*ws) <= 1e-8,
//             ws=4 for w=0.04; ws=24 => exact restart from t=0 with init).
// Lane k owns times 4k..4k+3 of a 128-elem segment: dense LDG/STG.128.
// Cross-lane coupling via 5-step shuffle affine scan (coeff a^4).
// Zero smem/barriers; 4-deep rotating load prefetch.

constexpr int T_LEN     = 6000;
constexpr int SEG       = 128;                 // 32 lanes x 4 floats
constexpr int NFULL     = T_LEN / SEG;         // 46 full segments (0..45)
constexpr int TAIL_SEG  = NFULL;               // segment 46: 112 elems
constexpr int REM_LANES = (T_LEN - NFULL*SEG) / 4;  // 28
constexpr int SPLIT_SEG = 24;                  // warp0 owns segs [0,24)
constexpr int WPB       = 4;                   // warps per block

__global__ __launch_bounds__(WPB * 32)
void ema_kernel(const float* __restrict__ x,
                const float* __restrict__ init,
                const float* __restrict__ wptr,
                float* __restrict__ out,
                int nseq)
{
    const int lane  = threadIdx.x & 31;
    const int gwarp = blockIdx.x * WPB + (threadIdx.x >> 5);
    const int seq   = gwarp >> 1;
    const int h     = gwarp & 1;
    if (seq >= nseq) return;                   // warp-uniform exit

    const float w  = fminf(fmaxf(wptr[0], 0.0f), 1.0f);
    const float a  = 1.0f - w;
    const float a2 = a * a;
    const float a3 = a2 * a;
    const float a4 = a2 * a2;
    const float alane = powf(a4, (float)lane);  // a^(4*lane)
    const float a128  = powf(a4, 32.0f);        // a^128

    // ---- per-warp segment range ----
    int s0, s1;          // process segments [s0, s1)
    int sstore;          // store only segments >= sstore
    bool use_init;
    if (h == 0) {
        s0 = 0; s1 = SPLIT_SEG; sstore = 0; use_init = true;
    } else {
        // warmup length: a^(128*ws) <= 1e-8  ->  ws = ceil(18.42/(128*(-ln a)))
        int ws;
        if (a <= 0.0f) {
            ws = 1;
        } else {
            float la = -logf(a);                // >= 0
            float need = 18.42f / (128.0f * la);
            ws = (need >= (float)SPLIT_SEG || !(need == need)) ? SPLIT_SEG
                                                               : (int)ceilf(need);
            if (ws < 1) ws = 1;
        }
        s0 = SPLIT_SEG - ws; s1 = NFULL + 1; sstore = SPLIT_SEG;
        use_init = (s0 == 0);
    }

    const float4* xp = reinterpret_cast<const float4*>(x + (size_t)seq * T_LEN);
    float4*       op = reinterpret_cast<float4*>(out + (size_t)seq * T_LEN);

    float carry = use_init ? init[seq] : 0.0f;

    // predicated dense segment load
    auto load_seg = [&](int j) -> float4 {
        bool ok = (j < s1) && (j < TAIL_SEG || lane < REM_LANES);
        return ok ? __ldcs(xp + j * 32 + lane) : make_float4(0.f, 0.f, 0.f, 0.f);
    };

    auto process = [&](float4 c, int segi) {
        float local0 = w * c.x;
        float local1 = fmaf(w, c.y, a * local0);
        float local2 = fmaf(w, c.z, a * local1);
        float local3 = fmaf(w, c.w, a * local2);

        // inclusive affine scan over lanes: D_l = e_l + a4 * D_{l-1}
        float D  = local3;
        float sc = a4;
        #pragma unroll
        for (int s = 1; s < 32; s <<= 1) {
            float p = __shfl_up_sync(0xffffffffu, D, s);
            if (lane >= s) D = fmaf(sc, p, D);
            sc *= sc;
        }
        float Dex = __shfl_up_sync(0xffffffffu, D, 1);
        if (lane == 0) Dex = 0.0f;
        float C   = fmaf(alane, carry, Dex);      // incoming state, this lane
        float D31 = __shfl_sync(0xffffffffu, D, 31);
        carry = fmaf(a128, carry, D31);           // state entering next segment

        bool store_ok = (segi >= sstore) &&
                        (segi < TAIL_SEG || lane < REM_LANES);
        if (store_ok) {
            float4 y = make_float4(fmaf(a,  C, local0),
                                   fmaf(a2, C, local1),
                                   fmaf(a3, C, local2),
                                   fmaf(a4, C, local3));
            __stcs(op + segi * 32 + lane, y);
        }
    };

    // 4-deep rotating prefetch
    float4 b0 = load_seg(s0 + 0);
    float4 b1 = load_seg(s0 + 1);
    float4 b2 = load_seg(s0 + 2);
    float4 b3 = load_seg(s0 + 3);

    #pragma unroll 1
    for (int i = s0; i < s1; i++) {
        float4 c = b0;
        b0 = b1; b1 = b2; b2 = b3;
        b3 = load_seg(i + 4);                  // issue before the scan chain
        process(c, i);
    }
}

extern "C" void kernel_launch(void* const* d_in, const int* in_sizes, int n_in,
                              void* d_out, int out_size)
{
    const float* x    = (const float*)d_in[0];   // mag_spec  [B,C,F,T]
    const float* init = (const float*)d_in[1];   // initial_state [B,C,F,1]
    const float* wp   = (const float*)d_in[2];   // weights [1]
    float*       out  = (float*)d_out;

    const int nseq   = in_sizes[1];              // B*C*F = 4112
    const int nwarps = nseq * 2;
    const int blocks = (nwarps + WPB - 1) / WPB; // 2056
    ema_kernel<<<blocks, WPB * 32>>>(x, init, wp, out, nseq);
}

// round 6
// speedup vs baseline: 1.0870x; 1.0870x over previous
#include <cuda_runtime.h>

// EMA along last axis: acc_t = w*x_t + (1-w)*acc_{t-1}
// [B,C,F,T] fp32, T=6000 contiguous; 4112 independent sequences.
//
// One WARP per sequence, 128-element segments (lane k owns times 4k..4k+3:
// every LDG.128/STG.128 is a dense 512B transaction). Cross-lane coupling
// via 5-step shuffle affine scan (coeff a^4). Carry chains in a register.
// Zero smem/barriers. 4-segment-deep load prefetch.
//
// R6 change vs R4: stores are normal write-back (evict-normal) instead of
// __stcs. Output (98.7MB) fits in L2 (126MB); across graph replays the
// dirty output lines stay L2-resident and are overwritten in place, cutting
// steady-state DRAM write traffic. Reads stay __ldcs (evict-first) so they
// do not displace the resident output.

constexpr int T_LEN     = 6000;
constexpr int SEG       = 128;                // 32 lanes x 4 floats
constexpr int NFULL     = T_LEN / SEG;        // 46
constexpr int REM       = T_LEN - NFULL*SEG;  // 112
constexpr int REM_LANES = REM / 4;            // 28
constexpr int WPB       = 4;                  // warps per block

__global__ __launch_bounds__(WPB * 32)
void ema_kernel(const float* __restrict__ x,
                const float* __restrict__ init,
                const float* __restrict__ wptr,
                float* __restrict__ out,
                int nseq)
{
    const int lane = threadIdx.x & 31;
    const int wid  = threadIdx.x >> 5;
    const int seq  = blockIdx.x * WPB + wid;
    if (seq >= nseq) return;                  // warp-uniform exit

    const float w  = fminf(fmaxf(wptr[0], 0.0f), 1.0f);
    const float a  = 1.0f - w;
    const float a2 = a * a;
    const float a3 = a2 * a;
    const float a4 = a2 * a2;
    const float alane = powf(a4, (float)lane);  // a^(4*lane)
    const float a128  = powf(a4, 32.0f);        // a^128

    const float4* xp = reinterpret_cast<const float4*>(x + (size_t)seq * T_LEN);
    float4*       op = reinterpret_cast<float4*>(out + (size_t)seq * T_LEN);

    float carry = init[seq];                  // state entering current segment

    // predicated dense segment load (seg j; j==NFULL is the 112-elem tail)
    auto load_seg = [&](int j) -> float4 {
        if (j < NFULL)                      return __ldcs(xp + j * 32 + lane);
        if (j == NFULL && lane < REM_LANES) return __ldcs(xp + j * 32 + lane);
        return make_float4(0.f, 0.f, 0.f, 0.f);
    };

    auto process = [&](float4 c, int segi, bool store_ok) {
        float local0 = w * c.x;
        float local1 = fmaf(w, c.y, a * local0);
        float local2 = fmaf(w, c.z, a * local1);
        float local3 = fmaf(w, c.w, a * local2);

        // inclusive affine scan over lanes: D_l = e_l + a4 * D_{l-1}
        float D  = local3;
        float sc = a4;
        #pragma unroll
        for (int s = 1; s < 32; s <<= 1) {
            float p = __shfl_up_sync(0xffffffffu, D, s);
            if (lane >= s) D = fmaf(sc, p, D);
            sc *= sc;
        }
        float Dex = __shfl_up_sync(0xffffffffu, D, 1);
        if (lane == 0) Dex = 0.0f;
        float C   = fmaf(alane, carry, Dex);      // incoming state, this lane
        float D31 = __shfl_sync(0xffffffffu, D, 31);
        carry = fmaf(a128, carry, D31);           // state entering next segment

        if (store_ok) {
            float4 y = make_float4(fmaf(a,  C, local0),
                                   fmaf(a2, C, local1),
                                   fmaf(a3, C, local2),
                                   fmaf(a4, C, local3));
            op[segi * 32 + lane] = y;             // write-back, evict-normal
        }
    };

    // 4-deep prefetch: b0..b3 hold segments i..i+3
    float4 b0 = load_seg(0);
    float4 b1 = load_seg(1);
    float4 b2 = load_seg(2);
    float4 b3 = load_seg(3);

    #pragma unroll 1
    for (int i = 0; i < NFULL; i += 2) {       // 23 iterations
        float4 c0 = b0, c1 = b1;
        b0 = b2; b1 = b3;
        // issue next loads BEFORE the serial scan chain
        b2 = load_seg(i + 4);
        b3 = load_seg(i + 5);
        process(c0, i,     true);
        process(c1, i + 1, true);
    }

    // tail segment 46 (112 elems) is sitting in b0 after the final shift
    process(b0, NFULL, lane < REM_LANES);
}

extern "C" void kernel_launch(void* const* d_in, const int* in_sizes, int n_in,
                              void* d_out, int out_size)
{
    const float* x    = (const float*)d_in[0];   // mag_spec  [B,C,F,T]
    const float* init = (const float*)d_in[1];   // initial_state [B,C,F,1]
    const float* wp   = (const float*)d_in[2];   // weights [1]
    float*       out  = (float*)d_out;

    const int nseq = in_sizes[1];                // B*C*F = 4112
    const int blocks = (nseq + WPB - 1) / WPB;   // 1028
    ema_kernel<<<blocks, WPB * 32>>>(x, init, wp, out, nseq);
}

// round 8
// speedup vs baseline: 1.1608x; 1.0679x over previous
#include <cuda_runtime.h>
#include <cstdint>

// EMA along last axis: acc_t = w*x_t + (1-w)*acc_{t-1}
// [B,C,F,T] fp32, T=6000 contiguous; 4112 independent sequences.
//
// One WARP per sequence, 128-element segments (lane k owns times 4k..4k+3:
// every LDG.128/STG.128 is a dense 512B transaction). Cross-lane coupling
// via 5-step shuffle affine scan (coeff a^4). Carry chains in a register.
// Zero smem/barriers. 4-segment-deep load prefetch.
//
// R8 = R7 intent with legal PTX: createpolicy + L2::cache_hint.
//   loads : evict_first policy (input streams through L2)
//   stores: evict_last  policy (output set, 98.7MB < 126MB L2, stays
//           resident across graph replays; overwritten in place next replay)

constexpr int T_LEN     = 6000;
constexpr int SEG       = 128;                // 32 lanes x 4 floats
constexpr int NFULL     = T_LEN / SEG;        // 46
constexpr int REM       = T_LEN - NFULL*SEG;  // 112
constexpr int REM_LANES = REM / 4;            // 28
constexpr int WPB       = 4;                  // warps per block

__device__ __forceinline__ float4 ldg_hint(const float4* p, uint64_t pol) {
    float4 v;
    asm("ld.global.L2::cache_hint.v4.f32 {%0,%1,%2,%3}, [%4], %5;"
        : "=f"(v.x), "=f"(v.y), "=f"(v.z), "=f"(v.w) : "l"(p), "l"(pol));
    return v;
}
__device__ __forceinline__ void stg_hint(float4* p, float4 v, uint64_t pol) {
    asm volatile("st.global.L2::cache_hint.v4.f32 [%0], {%1,%2,%3,%4}, %5;"
                 :: "l"(p), "f"(v.x), "f"(v.y), "f"(v.z), "f"(v.w), "l"(pol)
                 : "memory");
}

__global__ __launch_bounds__(WPB * 32)
void ema_kernel(const float* __restrict__ x,
                const float* __restrict__ init,
                const float* __restrict__ wptr,
                float* __restrict__ out,
                int nseq)
{
    const int lane = threadIdx.x & 31;
    const int wid  = threadIdx.x >> 5;
    const int seq  = blockIdx.x * WPB + wid;
    if (seq >= nseq) return;                  // warp-uniform exit

    uint64_t pol_first, pol_last;
    asm("createpolicy.fractional.L2::evict_first.b64 %0, 1.0;" : "=l"(pol_first));
    asm("createpolicy.fractional.L2::evict_last.b64 %0, 1.0;"  : "=l"(pol_last));

    const float w  = fminf(fmaxf(wptr[0], 0.0f), 1.0f);
    const float a  = 1.0f - w;
    const float a2 = a * a;
    const float a3 = a2 * a;
    const float a4 = a2 * a2;
    const float alane = powf(a4, (float)lane);  // a^(4*lane)
    const float a128  = powf(a4, 32.0f);        // a^128

    const float4* xp = reinterpret_cast<const float4*>(x + (size_t)seq * T_LEN);
    float4*       op = reinterpret_cast<float4*>(out + (size_t)seq * T_LEN);

    float carry = init[seq];                  // state entering current segment

    // predicated dense segment load (seg j; j==NFULL is the 112-elem tail)
    auto load_seg = [&](int j) -> float4 {
        if (j < NFULL)                      return ldg_hint(xp + j * 32 + lane, pol_first);
        if (j == NFULL && lane < REM_LANES) return ldg_hint(xp + j * 32 + lane, pol_first);
        return make_float4(0.f, 0.f, 0.f, 0.f);
    };

    auto process = [&](float4 c, int segi, bool store_ok) {
        float local0 = w * c.x;
        float local1 = fmaf(w, c.y, a * local0);
        float local2 = fmaf(w, c.z, a * local1);
        float local3 = fmaf(w, c.w, a * local2);

        // inclusive affine scan over lanes: D_l = e_l + a4 * D_{l-1}
        float D  = local3;
        float sc = a4;
        #pragma unroll
        for (int s = 1; s < 32; s <<= 1) {
            float p = __shfl_up_sync(0xffffffffu, D, s);
            if (lane >= s) D = fmaf(sc, p, D);
            sc *= sc;
        }
        float Dex = __shfl_up_sync(0xffffffffu, D, 1);
        if (lane == 0) Dex = 0.0f;
        float C   = fmaf(alane, carry, Dex);      // incoming state, this lane
        float D31 = __shfl_sync(0xffffffffu, D, 31);
        carry = fmaf(a128, carry, D31);           // state entering next segment

        if (store_ok) {
            float4 y = make_float4(fmaf(a,  C, local0),
                                   fmaf(a2, C, local1),
                                   fmaf(a3, C, local2),
                                   fmaf(a4, C, local3));
            stg_hint(op + segi * 32 + lane, y, pol_last);
        }
    };

    // 4-deep prefetch: b0..b3 hold segments i..i+3
    float4 b0 = load_seg(0);
    float4 b1 = load_seg(1);
    float4 b2 = load_seg(2);
    float4 b3 = load_seg(3);

    #pragma unroll 1
    for (int i = 0; i < NFULL; i += 2) {       // 23 iterations
        float4 c0 = b0, c1 = b1;
        b0 = b2; b1 = b3;
        // issue next loads BEFORE the serial scan chain
        b2 = load_seg(i + 4);
        b3 = load_seg(i + 5);
        process(c0, i,     true);
        process(c1, i + 1, true);
    }

    // tail segment 46 (112 elems) is sitting in b0 after the final shift
    process(b0, NFULL, lane < REM_LANES);
}

extern "C" void kernel_launch(void* const* d_in, const int* in_sizes, int n_in,
                              void* d_out, int out_size)
{
    const float* x    = (const float*)d_in[0];   // mag_spec  [B,C,F,T]
    const float* init = (const float*)d_in[1];   // initial_state [B,C,F,1]
    const float* wp   = (const float*)d_in[2];   // weights [1]
    float*       out  = (float*)d_out;

    const int nseq = in_sizes[1];                // B*C*F = 4112
    const int blocks = (nseq + WPB - 1) / WPB;   // 1028
    ema_kernel<<<blocks, WPB * 32>>>(x, init, wp, out, nseq);
}

// round 9
// speedup vs baseline: 1.1992x; 1.0331x over previous
#include <cuda_runtime.h>
#include <cstdint>

// EMA along last axis: acc_t = w*x_t + (1-w)*acc_{t-1}
// [B,C,F,T] fp32, T=6000 contiguous; 4112 independent sequences.
//
// One WARP per sequence, 256-element segments: lane k owns times 8k..8k+7,
// so every access is a 256-bit LDG.256/STG.256 (dense 1KB per warp op).
// Loads carry L2::evict_first (input streams through L2), stores carry
// L2::evict_last (output set, 98.7MB < 126MB L2, stays resident across
// graph replays). Cross-lane coupling via 5-step shuffle affine scan
// (coeff a^8). Carry chains in a register. Zero smem/barriers.
// 4-segment-deep prefetch (4KB in flight per warp).

constexpr int T_LEN = 6000;
constexpr int NF    = T_LEN / 256;          // 23 full segments
constexpr int REML  = (T_LEN - NF * 256) / 8;  // tail lanes: 14 (112 elems)
constexpr int WPB   = 4;                    // warps per block

struct F8 { float v[8]; };

__device__ __forceinline__ F8 ldg256_ef(const float* p) {
    F8 r;
    asm("ld.global.L2::evict_first.v8.b32 {%0,%1,%2,%3,%4,%5,%6,%7}, [%8];"
        : "=f"(r.v[0]), "=f"(r.v[1]), "=f"(r.v[2]), "=f"(r.v[3]),
          "=f"(r.v[4]), "=f"(r.v[5]), "=f"(r.v[6]), "=f"(r.v[7])
        : "l"(p));
    return r;
}
__device__ __forceinline__ void stg256_el(float* p, const F8& r) {
    asm volatile("st.global.L2::evict_last.v8.b32 [%0], {%1,%2,%3,%4,%5,%6,%7,%8};"
                 :: "l"(p),
                    "f"(r.v[0]), "f"(r.v[1]), "f"(r.v[2]), "f"(r.v[3]),
                    "f"(r.v[4]), "f"(r.v[5]), "f"(r.v[6]), "f"(r.v[7])
                 : "memory");
}
__device__ __forceinline__ F8 f8zero() {
    F8 r;
    #pragma unroll
    for (int i = 0; i < 8; i++) r.v[i] = 0.0f;
    return r;
}

__global__ __launch_bounds__(WPB * 32, 7)
void ema_kernel(const float* __restrict__ x,
                const float* __restrict__ init,
                const float* __restrict__ wptr,
                float* __restrict__ out,
                int nseq)
{
    const int lane = threadIdx.x & 31;
    const int wid  = threadIdx.x >> 5;
    const int seq  = blockIdx.x * WPB + wid;
    if (seq >= nseq) return;                   // warp-uniform exit

    const float w  = fminf(fmaxf(wptr[0], 0.0f), 1.0f);
    const float a  = 1.0f - w;

    // powers a^1..a^8
    float ap[9];
    ap[0] = 1.0f;
    #pragma unroll
    for (int k = 1; k <= 8; k++) ap[k] = ap[k - 1] * a;
    const float a8    = ap[8];
    const float alane = powf(a8, (float)lane);   // a^(8*lane)
    const float a256  = powf(a8, 32.0f);         // a^256

    const float* xs = x   + (size_t)seq * T_LEN;
    float*       os = out + (size_t)seq * T_LEN;

    float carry = init[seq];                    // state entering current segment

    // predicated dense segment load (seg j; j==NF is the 112-elem tail)
    auto load_seg = [&](int j) -> F8 {
        if (j < NF)                 return ldg256_ef(xs + j * 256 + lane * 8);
        if (j == NF && lane < REML) return ldg256_ef(xs + j * 256 + lane * 8);
        return f8zero();
    };

    auto process = [&](const F8& c, int segi, bool store_ok) {
        // local scan, zero init: 8 serial FMAs
        float loc[8];
        loc[0] = w * c.v[0];
        #pragma unroll
        for (int k = 1; k < 8; k++) loc[k] = fmaf(w, c.v[k], a * loc[k - 1]);

        // inclusive affine scan over lanes: D_l = e_l + a8 * D_{l-1}
        float D  = loc[7];
        float sc = a8;
        #pragma unroll
        for (int s = 1; s < 32; s <<= 1) {
            float p = __shfl_up_sync(0xffffffffu, D, s);
            if (lane >= s) D = fmaf(sc, p, D);
            sc *= sc;
        }
        float Dex = __shfl_up_sync(0xffffffffu, D, 1);
        if (lane == 0) Dex = 0.0f;
        float C   = fmaf(alane, carry, Dex);       // incoming state, this lane
        float D31 = __shfl_sync(0xffffffffu, D, 31);
        carry = fmaf(a256, carry, D31);            // state entering next segment

        if (store_ok) {
            F8 y;
            #pragma unroll
            for (int k = 0; k < 8; k++) y.v[k] = fmaf(ap[k + 1], C, loc[k]);
            stg256_el(os + segi * 256 + lane * 8, y);
        }
    };

    // 4-deep prefetch: b0..b3 hold segments i..i+3 (4KB in flight per warp)
    F8 b0 = load_seg(0);
    F8 b1 = load_seg(1);
    F8 b2 = load_seg(2);
    F8 b3 = load_seg(3);

    #pragma unroll 1
    for (int i = 0; i < NF - 1; i += 2) {       // 11 iters, segs 0..21
        F8 c0 = b0, c1 = b1;
        b0 = b2; b1 = b3;
        // issue next loads BEFORE the serial scan chain
        b2 = load_seg(i + 4);
        b3 = load_seg(i + 5);
        process(c0, i,     true);
        process(c1, i + 1, true);
    }

    // after loop: b0 = seg 22 (last full), b1 = seg 23 (112-elem tail)
    process(b0, NF - 1, true);
    process(b1, NF,     lane < REML);
}

extern "C" void kernel_launch(void* const* d_in, const int* in_sizes, int n_in,
                              void* d_out, int out_size)
{
    const float* x    = (const float*)d_in[0];   // mag_spec  [B,C,F,T]
    const float* init = (const float*)d_in[1];   // initial_state [B,C,F,1]
    const float* wp   = (const float*)d_in[2];   // weights [1]
    float*       out  = (float*)d_out;

    const int nseq = in_sizes[1];                // B*C*F = 4112
    const int blocks = (nseq + WPB - 1) / WPB;   // 1028
    ema_kernel<<<blocks, WPB * 32>>>(x, init, wp, out, nseq);
}

// round 10
// speedup vs baseline: 1.2060x; 1.0057x over previous
#include <cuda_runtime.h>
#include <cstdint>

// EMA along last axis: acc_t = w*x_t + (1-w)*acc_{t-1}
// [B,C,F,T] fp32, T=6000 contiguous; 4112 independent sequences.
//
// One WARP per sequence, 128-element segments (lane k owns times 4k..4k+3:
// dense 512B LDG/STG.128). L2 policy: loads evict_first (input streams),
// stores evict_last (output 98.7MB < 126MB L2 stays resident across graph
// replays). Cross-lane coupling via shuffle affine scan (coeff a^4).
//
// R10 vs R8: FOUR segments processed per iteration with the 5-step shuffle
// scans INTERLEAVED across 4 independent chains (hides SHFL latency ~3x).
// Output recomputed by re-running the exact recurrence seeded with the
// incoming state C (saves 16 regs vs caching the local scan).

constexpr int T_LEN = 6000;
constexpr int NFULL = T_LEN / 128;          // 46 full segments
constexpr int REML  = (T_LEN - NFULL*128) / 4;  // 28 tail lanes (112 elems)
constexpr int WPB   = 4;                    // warps per block

__device__ __forceinline__ float4 ldg_hint(const float4* p, uint64_t pol) {
    float4 v;
    asm("ld.global.L2::cache_hint.v4.f32 {%0,%1,%2,%3}, [%4], %5;"
        : "=f"(v.x), "=f"(v.y), "=f"(v.z), "=f"(v.w) : "l"(p), "l"(pol));
    return v;
}
__device__ __forceinline__ void stg_hint(float4* p, float4 v, uint64_t pol) {
    asm volatile("st.global.L2::cache_hint.v4.f32 [%0], {%1,%2,%3,%4}, %5;"
                 :: "l"(p), "f"(v.x), "f"(v.y), "f"(v.z), "f"(v.w), "l"(pol)
                 : "memory");
}

__global__ __launch_bounds__(WPB * 32, 7)
void ema_kernel(const float* __restrict__ x,
                const float* __restrict__ init,
                const float* __restrict__ wptr,
                float* __restrict__ out,
                int nseq)
{
    const int lane = threadIdx.x & 31;
    const int wid  = threadIdx.x >> 5;
    const int seq  = blockIdx.x * WPB + wid;
    if (seq >= nseq) return;                  // warp-uniform exit

    uint64_t pol_first, pol_last;
    asm("createpolicy.fractional.L2::evict_first.b64 %0, 1.0;" : "=l"(pol_first));
    asm("createpolicy.fractional.L2::evict_last.b64 %0, 1.0;"  : "=l"(pol_last));

    const float w  = fminf(fmaxf(wptr[0], 0.0f), 1.0f);
    const float a  = 1.0f - w;
    const float a4 = (a * a) * (a * a);
    const float alane = powf(a4, (float)lane);  // a^(4*lane)
    const float a128  = powf(a4, 32.0f);        // a^128

    const float4* xp = reinterpret_cast<const float4*>(x + (size_t)seq * T_LEN);
    float4*       op = reinterpret_cast<float4*>(out + (size_t)seq * T_LEN);

    float carry = init[seq];                   // state entering current segment

    auto load_seg = [&](int j) -> float4 {
        bool ok = (j < NFULL) || (j == NFULL && lane < REML);
        return ok ? ldg_hint(xp + j * 32 + lane, pol_first)
                  : make_float4(0.f, 0.f, 0.f, 0.f);
    };

    // process 4 consecutive segments with interleaved lane scans
    auto scan4 = [&](float4 c0, float4 c1, float4 c2, float4 c3, int base) {
        float4 cc[4] = { c0, c1, c2, c3 };

        // 4 independent local chains (zero init) -> chunk sums D[j]
        float D[4];
        #pragma unroll
        for (int j = 0; j < 4; j++) {
            float t = w * cc[j].x;
            t = fmaf(w, cc[j].y, a * t);
            t = fmaf(w, cc[j].z, a * t);
            t = fmaf(w, cc[j].w, a * t);
            D[j] = t;
        }

        // interleaved inclusive affine scans: D_l = e_l + a4 * D_{l-1}
        float sc = a4;
        #pragma unroll
        for (int s = 1; s < 32; s <<= 1) {
            float p0 = __shfl_up_sync(0xffffffffu, D[0], s);
            float p1 = __shfl_up_sync(0xffffffffu, D[1], s);
            float p2 = __shfl_up_sync(0xffffffffu, D[2], s);
            float p3 = __shfl_up_sync(0xffffffffu, D[3], s);
            if (lane >= s) {
                D[0] = fmaf(sc, p0, D[0]);
                D[1] = fmaf(sc, p1, D[1]);
                D[2] = fmaf(sc, p2, D[2]);
                D[3] = fmaf(sc, p3, D[3]);
            }
            sc *= sc;
        }

        float Dex[4], D31[4];
        #pragma unroll
        for (int j = 0; j < 4; j++) {
            Dex[j] = __shfl_up_sync(0xffffffffu, D[j], 1);
            if (lane == 0) Dex[j] = 0.0f;
            D31[j] = __shfl_sync(0xffffffffu, D[j], 31);
        }

        // serial carry coupling (4 FMAs) -> incoming state C[j] per segment
        float C[4];
        float cj = carry;
        #pragma unroll
        for (int j = 0; j < 4; j++) {
            C[j] = fmaf(alane, cj, Dex[j]);
            cj   = fmaf(a128,  cj, D31[j]);
        }
        carry = cj;

        // recompute outputs via the exact recurrence seeded with C[j]
        #pragma unroll
        for (int j = 0; j < 4; j++) {
            int segi = base + j;
            bool ok = (segi < NFULL) || (segi == NFULL && lane < REML);
            if (ok) {
                float t = C[j];
                float4 y;
                t = fmaf(w, cc[j].x, a * t); y.x = t;
                t = fmaf(w, cc[j].y, a * t); y.y = t;
                t = fmaf(w, cc[j].z, a * t); y.z = t;
                t = fmaf(w, cc[j].w, a * t); y.w = t;
                stg_hint(op + segi * 32 + lane, y, pol_last);
            }
        }
    };

    // prefetch segments 0..3
    float4 b0 = load_seg(0);
    float4 b1 = load_seg(1);
    float4 b2 = load_seg(2);
    float4 b3 = load_seg(3);

    #pragma unroll 1
    for (int i = 0; i < 44; i += 4) {          // 11 iters: segs 0..43
        float4 c0 = b0, c1 = b1, c2 = b2, c3 = b3;
        b0 = load_seg(i + 4);                  // loads lead the scan chains
        b1 = load_seg(i + 5);
        b2 = load_seg(i + 6);
        b3 = load_seg(i + 7);
        scan4(c0, c1, c2, c3, i);
    }

    // epilogue: segs 44, 45, 46(tail, lane<REML), 47(predicated off)
    scan4(b0, b1, b2, b3, 44);
}

extern "C" void kernel_launch(void* const* d_in, const int* in_sizes, int n_in,
                              void* d_out, int out_size)
{
    const float* x    = (const float*)d_in[0];   // mag_spec  [B,C,F,T]
    const float* init = (const float*)d_in[1];   // initial_state [B,C,F,1]
    const float* wp   = (const float*)d_in[2];   // weights [1]
    float*       out  = (float*)d_out;

    const int nseq = in_sizes[1];                // B*C*F = 4112
    const int blocks = (nseq + WPB - 1) / WPB;   // 1028
    ema_kernel<<<blocks, WPB * 32>>>(x, init, wp, out, nseq);
}